// round 1
// baseline (speedup 1.0000x reference)
#include <cuda_runtime.h>
#include <cuda_bf16.h>

// Problem constants (shapes fixed by the dataset)
#define DIMV 128
#define NTYPES 32
#define MAXV 50048            // padded a bit above 50000

// Scratch: projected node features (dense precompute, reused ~12.8x per node)
__device__ float g_src_proj[(size_t)MAXV * DIMV];
__device__ float g_dest_proj[(size_t)MAXV * DIMV];

// ---------------------------------------------------------------------------
// Zero the output (d_out is poisoned by the harness; segment_sum implies 0 init)
// ---------------------------------------------------------------------------
__global__ void zero_kernel(float4* __restrict__ out, int n4) {
    int i = blockIdx.x * blockDim.x + threadIdx.x;
    if (i < n4) out[i] = make_float4(0.f, 0.f, 0.f, 0.f);
}

// ---------------------------------------------------------------------------
// Fused dual projection: src_proj = nv @ W_src + b_src ; dest_proj = nv @ W_dest + b_dest
// Block: 256 threads, 32 node-rows per block.
//   t = tid & 127  -> output dim
//   half = tid>>7  -> which 16 rows this thread accumulates (32 indep accumulators)
// Smem: both W matrices (128KB) + node tile (16KB) = 147456 B dynamic smem.
// ---------------------------------------------------------------------------
#define ROWS_PB 32
#define RPT 16
#define PROJ_SMEM (2 * 128 * 128 * 4 + ROWS_PB * 128 * 4)

__global__ __launch_bounds__(256) void proj_kernel(
    const float* __restrict__ nv, int V,
    const float* __restrict__ Wsrc, const float* __restrict__ bsrc,
    const float* __restrict__ Wdst, const float* __restrict__ bdst)
{
    extern __shared__ float sm[];
    float* Ws = sm;                    // [128][128] row k, col t
    float* Wd = sm + 128 * 128;        // [128][128]
    float* Xs = sm + 2 * 128 * 128;    // [32][128] node tile

    const int tid = threadIdx.x;
    // Load both weight matrices (coalesced)
    for (int i = tid; i < 128 * 128; i += 256) {
        Ws[i] = Wsrc[i];
        Wd[i] = Wdst[i];
    }
    const int row0 = blockIdx.x * ROWS_PB;
    for (int i = tid; i < ROWS_PB * 128; i += 256) {
        int r = row0 + (i >> 7);
        Xs[i] = (r < V) ? nv[(size_t)r * 128 + (i & 127)] : 0.f;
    }
    __syncthreads();

    const int t = tid & 127;
    const int rbase = (tid >> 7) * RPT;

    float accs[RPT], accd[RPT];
    const float bs = bsrc[t];
    const float bd = bdst[t];
#pragma unroll
    for (int i = 0; i < RPT; i++) { accs[i] = bs; accd[i] = bd; }

    for (int k = 0; k < 128; k += 4) {
        const float ws0 = Ws[(k + 0) * 128 + t];
        const float ws1 = Ws[(k + 1) * 128 + t];
        const float ws2 = Ws[(k + 2) * 128 + t];
        const float ws3 = Ws[(k + 3) * 128 + t];
        const float wd0 = Wd[(k + 0) * 128 + t];
        const float wd1 = Wd[(k + 1) * 128 + t];
        const float wd2 = Wd[(k + 2) * 128 + t];
        const float wd3 = Wd[(k + 3) * 128 + t];
#pragma unroll
        for (int i = 0; i < RPT; i++) {
            float4 x = *reinterpret_cast<const float4*>(&Xs[(rbase + i) * 128 + k]);
            accs[i] = fmaf(x.x, ws0, accs[i]);
            accs[i] = fmaf(x.y, ws1, accs[i]);
            accs[i] = fmaf(x.z, ws2, accs[i]);
            accs[i] = fmaf(x.w, ws3, accs[i]);
            accd[i] = fmaf(x.x, wd0, accd[i]);
            accd[i] = fmaf(x.y, wd1, accd[i]);
            accd[i] = fmaf(x.z, wd2, accd[i]);
            accd[i] = fmaf(x.w, wd3, accd[i]);
        }
    }

#pragma unroll
    for (int i = 0; i < RPT; i++) {
        int r = row0 + rbase + i;
        if (r < V) {
            g_src_proj[(size_t)r * 128 + t]  = accs[i];
            g_dest_proj[(size_t)r * 128 + t] = accd[i];
        }
    }
}

// ---------------------------------------------------------------------------
// Edge kernel: warp per 32 edges (coalesced index loads, shfl broadcast).
// Each lane owns a 4-float (float4) chunk of the 128-dim message.
// msg = relu(src_proj[s] + dest_proj[d] + emb[c]) ; red.add.v4 into out[d].
// ---------------------------------------------------------------------------
__global__ __launch_bounds__(256) void edge_kernel(
    const int* __restrict__ esrc, const int* __restrict__ edst,
    const int* __restrict__ ecls, const float* __restrict__ emb,
    float* __restrict__ out, int E)
{
    __shared__ float4 emb_sm[NTYPES * 32];   // 16 KB, whole embedding table
    const int tid = threadIdx.x;
    for (int i = tid; i < NTYPES * 32; i += 256)
        emb_sm[i] = reinterpret_cast<const float4*>(emb)[i];
    __syncthreads();

    const int lane = tid & 31;
    const int warp_g = (blockIdx.x * 256 + tid) >> 5;
    const int ebase = warp_g * 32;
    if (ebase >= E) return;

    const int myE = ebase + lane;
    int s_l = 0, d_l = 0, c_l = 0;
    if (myE < E) {
        s_l = esrc[myE];
        d_l = edst[myE];
        c_l = ecls[myE];
    }
    const int cnt = min(32, E - ebase);

    const float4* __restrict__ sp = reinterpret_cast<const float4*>(g_src_proj);
    const float4* __restrict__ dp = reinterpret_cast<const float4*>(g_dest_proj);

    for (int j = 0; j < cnt; j++) {
        const int s = __shfl_sync(0xffffffffu, s_l, j);
        const int d = __shfl_sync(0xffffffffu, d_l, j);
        const int c = __shfl_sync(0xffffffffu, c_l, j);

        float4 a = sp[s * 32 + lane];
        float4 b = dp[d * 32 + lane];
        float4 e = emb_sm[c * 32 + lane];
        float4 m;
        m.x = fmaxf(a.x + b.x + e.x, 0.f);
        m.y = fmaxf(a.y + b.y + e.y, 0.f);
        m.z = fmaxf(a.z + b.z + e.z, 0.f);
        m.w = fmaxf(a.w + b.w + e.w, 0.f);

        float* op = out + ((size_t)d * 128 + lane * 4);
        asm volatile("red.global.add.v4.f32 [%0], {%1,%2,%3,%4};"
                     :: "l"(op), "f"(m.x), "f"(m.y), "f"(m.z), "f"(m.w)
                     : "memory");
    }
}

// ---------------------------------------------------------------------------
// Launch
// Inputs (metadata order): node_values, edge_src, edge_dest, edge_cls,
//                          W_src, b_src, W_dest, b_dest, edge_emb
// ---------------------------------------------------------------------------
extern "C" void kernel_launch(void* const* d_in, const int* in_sizes, int n_in,
                              void* d_out, int out_size) {
    const float* nv   = (const float*)d_in[0];
    const int*   esrc = (const int*)  d_in[1];
    const int*   edst = (const int*)  d_in[2];
    const int*   ecls = (const int*)  d_in[3];
    const float* Wsrc = (const float*)d_in[4];
    const float* bsrc = (const float*)d_in[5];
    const float* Wdst = (const float*)d_in[6];
    const float* bdst = (const float*)d_in[7];
    const float* emb  = (const float*)d_in[8];
    float* out = (float*)d_out;

    const int V = in_sizes[0] / DIMV;
    const int E = in_sizes[1];

    // Allow >48KB dynamic smem for the projection kernel (host-side, not captured)
    cudaFuncSetAttribute(proj_kernel, cudaFuncAttributeMaxDynamicSharedMemorySize,
                         PROJ_SMEM);

    // 1) zero output
    {
        int n4 = out_size / 4;
        int blocks = (n4 + 255) / 256;
        zero_kernel<<<blocks, 256>>>((float4*)out, n4);
    }
    // 2) dual projection
    {
        int blocks = (V + ROWS_PB - 1) / ROWS_PB;
        proj_kernel<<<blocks, 256, PROJ_SMEM>>>(nv, V, Wsrc, bsrc, Wdst, bdst);
    }
    // 3) edge gather + relu + scatter-add
    {
        int blocks = (E + 255) / 256;   // 256 edges per block (8 warps x 32)
        edge_kernel<<<blocks, 256>>>(esrc, edst, ecls, emb, out, E);
    }
}